// round 6
// baseline (speedup 1.0000x reference)
#include <cuda_runtime.h>
#include <cuda_bf16.h>
#include <cstdint>

// ---------------------------------------------------------------------------
// MultiLevelFeatureSampler on GB300 (sm_103a via base-target sm_103 SASS)
//
// Per point: D[128x256] = P[128x83] @ W^T (+ bias); P = gather of 83 taps.
// fp32 via split-bf16: D = Ah*Bh + Ah*Bl + Al*Bh, HMMA m16n8k16 fp32 accum.
//
// R6: persistent CTAs (grid=148), 512 threads, WARP-SPECIALIZED:
//   warps 0-7  = MMA group   (GEMM on A[cur] + epilogue)
//   warps 8-15 = gather group (taps + gather/convert point p+1 into A[cur^1])
// running concurrently; one __syncthreads per point to swap buffers.
// B (both split halves) resident in smem for the CTA lifetime.
// ---------------------------------------------------------------------------

#define NSM   148
#define NPTS_TOTAL 2048
#define CCH   128
#define DTOT  83
#define GTOT  (CCH * DTOT)     // 10624 gather elements per point
#define STRD  104              // row stride in bf16 (208 B, ldmatrix conflict-free)
#define NOUT  256

#define H0 93
#define W0 305
#define H1 47
#define W1 153
#define H2 24
#define W2 77

// ---- smem layout (bytes) ----
#define OFF_TAPP    0                              // 83 * 8B tap base pointers
#define OFF_TAPS    672                            // 83 * 4B channel strides
#define OFF_BIAS    1008                           // 256 * 4B
#define OFF_A0      2048
#define AL_OFF      (CCH * STRD * 2)               // 26624 (Ah->Al within buffer)
#define ABUF        (2 * AL_OFF)                   // 53248
#define OFF_BH      (OFF_A0 + 2 * ABUF)            // 108544 (256 x 208B)
#define OFF_BL      (OFF_BH + NOUT * STRD * 2)     // 161792
#define SMEM_TOTAL  (OFF_BL + NOUT * STRD * 2)     // 215040 (~210 KB)

// W split-bf16 scratch, [0]=hi, [1]=lo, row-major 256 x STRD (pads zeroed)
__device__ __align__(16) __nv_bfloat16 g_B[2][NOUT * STRD];

// ---------------------------------------------------------------------------
__device__ __forceinline__ uint32_t smem_u32(const void* p) {
    uint32_t a;
    asm("{ .reg .u64 t; cvta.to.shared.u64 t, %1; cvt.u32.u64 %0, t; }"
        : "=r"(a) : "l"(p));
    return a;
}

__device__ __forceinline__ void cp16(uint32_t dst, const void* src) {
    asm volatile("cp.async.cg.shared.global [%0], [%1], 16;"
                 :: "r"(dst), "l"(src) : "memory");
}

__device__ __forceinline__ void ldsm4(uint32_t* r, uint32_t addr) {
    asm volatile("ldmatrix.sync.aligned.m8n8.x4.shared.b16 {%0,%1,%2,%3}, [%4];"
                 : "=r"(r[0]), "=r"(r[1]), "=r"(r[2]), "=r"(r[3]) : "r"(addr));
}

__device__ __forceinline__ void hmma(float* c, const uint32_t* a, const uint32_t* b) {
    asm volatile(
        "mma.sync.aligned.m16n8k16.row.col.f32.bf16.bf16.f32 "
        "{%0,%1,%2,%3}, {%4,%5,%6,%7}, {%8,%9}, {%0,%1,%2,%3};"
        : "+f"(c[0]), "+f"(c[1]), "+f"(c[2]), "+f"(c[3])
        : "r"(a[0]), "r"(a[1]), "r"(a[2]), "r"(a[3]), "r"(b[0]), "r"(b[1]));
}

// Per-tap gather metadata for point pn (called with d < 83)
__device__ __forceinline__ void compute_taps(char* smem, int d, int pn,
                                             const float* __restrict__ points,
                                             const float* __restrict__ feat0,
                                             const float* __restrict__ feat1,
                                             const float* __restrict__ feat2) {
    const float* f; int H, Wd, ks, dd;
    if (d < 49)      { f = feat0; H = H0; Wd = W0; ks = 7; dd = d; }
    else if (d < 74) { f = feat1; H = H1; Wd = W1; ks = 5; dd = d - 49; }
    else             { f = feat2; H = H2; Wd = W2; ks = 3; dd = d - 74; }
    int half = ks >> 1;
    int jj = dd / ks - half;
    int kk = dd % ks - half;
    int bi = pn >> 9;
    float px = points[pn * 2 + 0];
    float py = points[pn * 2 + 1];
    float x = fminf(fmaxf(px * (float)(Wd - 1), 0.f), (float)(Wd - 1));
    float y = fminf(fmaxf(py * (float)(H  - 1), 0.f), (float)(H  - 1));
    int ox = (int)floorf(fminf(fmaxf(x + (float)kk, 0.f), (float)(Wd - 1)));
    int oy = (int)floorf(fminf(fmaxf(y + (float)jj, 0.f), (float)(H  - 1)));
    *(int*)(smem + OFF_TAPS + d * 4) = H * Wd;
    *(const float**)(smem + OFF_TAPP + d * 8) =
        f + (size_t)bi * CCH * H * Wd + (oy * Wd + ox);
}

// Gather + split-convert one point into buffer bufH/bufL. 256 threads (gtid).
__device__ __forceinline__ void gather_point(char* smem, char* bufH, char* bufL,
                                             int gtid) {
    // e = c*83 + d walks e = gtid + 256*i;  256 = 3*83 + 7
    int c = gtid / DTOT;        // gtid < 256 -> c in 0..3
    int d = gtid - c * DTOT;
    #pragma unroll 1
    for (int base = 0; base < GTOT; base += 256 * 7) {
        float v[7]; int cc[7], dd[7]; bool ok[7];
        #pragma unroll
        for (int j = 0; j < 7; ++j) {
            int e = gtid + base + j * 256;
            ok[j] = (e < GTOT);
            if (ok[j]) {
                const float* bp = *(const float* const*)(smem + OFF_TAPP + d * 8);
                int st = *(const int*)(smem + OFF_TAPS + d * 4);
                v[j] = __ldg(bp + (size_t)c * st);
                cc[j] = c; dd[j] = d;
            }
            c += 3; d += 7;
            if (d >= DTOT) { d -= DTOT; c += 1; }
        }
        #pragma unroll
        for (int j = 0; j < 7; ++j) {
            if (ok[j]) {
                __nv_bfloat16 hi = __float2bfloat16(v[j]);
                __nv_bfloat16 lo = __float2bfloat16(v[j] - __bfloat162float(hi));
                int sw = cc[j] * 208 + dd[j] * 2;
                *(__nv_bfloat16*)(bufH + sw) = hi;
                *(__nv_bfloat16*)(bufL + sw) = lo;
            }
        }
    }
}

// ---------------------------------------------------------------------------
// Prologue: W (256x83 fp32) -> g_B hi/lo bf16, row stride STRD, pads zeroed.
__global__ void prep_B_kernel(const float* __restrict__ Wg) {
    int idx = blockIdx.x * 256 + threadIdx.x;
    if (idx >= NOUT * STRD) return;
    int row = idx / STRD;
    int col = idx - row * STRD;
    float v = (col < DTOT) ? Wg[row * DTOT + col] : 0.f;
    __nv_bfloat16 hi = __float2bfloat16(v);
    __nv_bfloat16 lo = __float2bfloat16(v - __bfloat162float(hi));
    g_B[0][idx] = hi;
    g_B[1][idx] = lo;
}

// ---------------------------------------------------------------------------
__global__ void __launch_bounds__(512, 1)
mlfs_kernel(const float* __restrict__ points,
            const float* __restrict__ feat0,
            const float* __restrict__ feat1,
            const float* __restrict__ feat2,
            const float* __restrict__ biasg,
            float* __restrict__ out) {
    extern __shared__ char smem[];
    const uint32_t smem_base = smem_u32(smem);
    const int tid = threadIdx.x;
    const int lane = tid & 31;
    const int r = blockIdx.x;

    // ---- setup: B resident copy (async) by all threads; bias ----
    {
        const char* src = (const char*)g_B;
        uint32_t dst = smem_base + OFF_BH;
        const int n16 = (2 * NOUT * STRD * 2) / 16;   // 6656
        for (int i = tid; i < n16; i += 512)
            cp16(dst + i * 16, src + (size_t)i * 16);
        asm volatile("cp.async.commit_group;" ::: "memory");
    }
    if (tid < 64)
        ((float4*)(smem + OFF_BIAS))[tid] = ((const float4*)biasg)[tid];

    if (tid >= 256) {
        const int gtid = tid - 256;
        // zero A pad bytes 160..207 of every row (cols 80..103), both buffers
        // x (Ah, Al): 512 rows, 2 per thread
        float4 z = make_float4(0.f, 0.f, 0.f, 0.f);
        #pragma unroll
        for (int q = 0; q < 2; ++q) {
            int row = gtid + q * 256;
            char* base = smem + OFF_A0 + (row >> 7) * AL_OFF + (row & 127) * 208 + 160;
            ((float4*)base)[0] = z; ((float4*)base)[1] = z; ((float4*)base)[2] = z;
        }
        // taps + gather for first point into buf 0
        if (gtid < DTOT)
            compute_taps(smem, gtid, r, points, feat0, feat1, feat2);
        asm volatile("bar.sync 1, 256;" ::: "memory");
        gather_point(smem, smem + OFF_A0, smem + OFF_A0 + AL_OFF, gtid);
    }
    asm volatile("cp.async.wait_group 0;" ::: "memory");

    // ---- persistent loop: MMA group computes A[cur], gather group fills A[cur^1]
    int cur = 0;
    for (int p = r; p < NPTS_TOTAL; p += NSM) {
        __syncthreads();   // A[cur] gathered; MMA done reading A[cur^1]

        if (tid < 256) {
            // ================= MMA group =================
            const int wid = tid >> 5;
            const int wm = wid >> 2;            // 0..1 (M)
            const int wn = wid & 3;             // 0..3 (N within 128-col half)
            const uint32_t lrow = lane & 15;
            const uint32_t kof2 = ((lane >> 4) << 3) * 2;
            const uint32_t aCur = smem_base + OFF_A0 + cur * ABUF;
            float* outp = out + (size_t)p * (CCH * NOUT);
            const float* bs = (const float*)(smem + OFF_BIAS);

            #pragma unroll
            for (int hh = 0; hh < 2; ++hh) {
                float acc[4][4][4];
                #pragma unroll
                for (int mt = 0; mt < 4; ++mt)
                    #pragma unroll
                    for (int nt = 0; nt < 4; ++nt)
                        #pragma unroll
                        for (int q = 0; q < 4; ++q) acc[mt][nt][q] = 0.f;

                #pragma unroll
                for (int pass = 0; pass < 3; ++pass) {
                    uint32_t aAddr0 = aCur + ((pass == 2) ? AL_OFF : 0)
                                    + (wm * 64 + lrow) * 208 + kof2;
                    uint32_t bAddr0 = smem_base + ((pass == 1) ? OFF_BL : OFF_BH)
                                    + (hh * 128 + wn * 32 + lrow) * 208 + kof2;
                    #pragma unroll
                    for (int ks = 0; ks < 6; ++ks) {
                        uint32_t a[4][4], b[4][2], t[4];
                        #pragma unroll
                        for (int mt = 0; mt < 4; ++mt)
                            ldsm4(a[mt], aAddr0 + mt * 16 * 208 + ks * 32);
                        #pragma unroll
                        for (int np = 0; np < 2; ++np) {
                            ldsm4(t, bAddr0 + np * 16 * 208 + ks * 32);
                            b[2 * np + 0][0] = t[0]; b[2 * np + 1][0] = t[1];
                            b[2 * np + 0][1] = t[2]; b[2 * np + 1][1] = t[3];
                        }
                        #pragma unroll
                        for (int mt = 0; mt < 4; ++mt)
                            #pragma unroll
                            for (int nt = 0; nt < 4; ++nt)
                                hmma(acc[mt][nt], a[mt], b[nt]);
                    }
                }

                // epilogue for this 128-col half
                const int r0 = wm * 64 + (lane >> 2);
                const int c0 = wn * 32 + 2 * (lane & 3);
                float2 bv[4];
                #pragma unroll
                for (int nt = 0; nt < 4; ++nt)
                    bv[nt] = *(const float2*)(bs + hh * 128 + c0 + nt * 8);
                float* oph = outp + hh * 128;
                #pragma unroll
                for (int mt = 0; mt < 4; ++mt) {
                    const int row = r0 + mt * 16;
                    #pragma unroll
                    for (int nt = 0; nt < 4; ++nt) {
                        const int col = c0 + nt * 8;
                        float2 v0, v1;
                        v0.x = acc[mt][nt][0] + bv[nt].x;
                        v0.y = acc[mt][nt][1] + bv[nt].y;
                        v1.x = acc[mt][nt][2] + bv[nt].x;
                        v1.y = acc[mt][nt][3] + bv[nt].y;
                        *(float2*)(oph + (size_t)row * NOUT + col) = v0;
                        *(float2*)(oph + (size_t)(row + 8) * NOUT + col) = v1;
                    }
                }
            }
        } else {
            // ================= gather group =================
            const int gtid = tid - 256;
            const int pn = p + NSM;
            if (pn < NPTS_TOTAL) {
                if (gtid < DTOT)
                    compute_taps(smem, gtid, pn, points, feat0, feat1, feat2);
                asm volatile("bar.sync 1, 256;" ::: "memory");
                char* nb = smem + OFF_A0 + (cur ^ 1) * ABUF;
                gather_point(smem, nb, nb + AL_OFF, gtid);
            }
        }

        cur ^= 1;
    }
}

// ---------------------------------------------------------------------------
extern "C" void kernel_launch(void* const* d_in, const int* in_sizes, int n_in,
                              void* d_out, int out_size) {
    const float* points = (const float*)d_in[0];
    const float* feat0  = (const float*)d_in[1];
    const float* feat1  = (const float*)d_in[2];
    const float* feat2  = (const float*)d_in[3];
    const float* Wg     = (const float*)d_in[4];
    const float* biasg  = (const float*)d_in[5];
    float* out = (float*)d_out;

    prep_B_kernel<<<(NOUT * STRD + 255) / 256, 256>>>(Wg);

    cudaFuncSetAttribute(mlfs_kernel,
                         cudaFuncAttributeMaxDynamicSharedMemorySize, SMEM_TOTAL);
    mlfs_kernel<<<NSM, 512, SMEM_TOTAL>>>(points, feat0, feat1, feat2,
                                          biasg, out);
}

// round 8
// speedup vs baseline: 1.6651x; 1.6651x over previous
#include <cuda_runtime.h>
#include <cuda_bf16.h>
#include <cstdint>

// ---------------------------------------------------------------------------
// MultiLevelFeatureSampler on GB300 (sm_103a via base-target sm_103 SASS)
//
// Per point: D[128x256] = P[128x83] @ W^T (+ bias); P = gather of 83 taps.
// fp32 via split-bf16: D = Ah*Bh + Ah*Bl + Al*Bh, HMMA m16n8k16 fp32 accum.
//
// R7: persistent CTAs (grid=148, 256 thr, uniform warps).  Gather of point
// p+1 issued as fire-and-forget cp.async (4B) into a raw fp32 smem buffer
// during the MMA window of point p (no scoreboard stalls, no registers held).
// Exposed per-point work = convert phase (raw -> split-bf16, LDS/STS
// throughput bound) only.  Output stored with st.global.cs so the 256MB
// stream does not evict the 76MB feature maps from L2 (gather stays L2-hit).
// ---------------------------------------------------------------------------

#define NSM   148
#define NPTS_TOTAL 2048
#define CCH   128
#define DTOT  83
#define GTOT  (CCH * DTOT)     // 10624 gather elements per point
#define STRD  104              // row stride in bf16 (208 B, ldmatrix conflict-free)
#define NOUT  256

#define H0 93
#define W0 305
#define H1 47
#define W1 153
#define H2 24
#define W2 77

// ---- smem layout (bytes) ----
#define OFF_TAPP    0                              // 83 * 8B tap base pointers
#define OFF_TAPS    672                            // 83 * 4B channel strides
#define OFF_BIAS    1008                           // 256 * 4B -> ends 2032
#define OFF_A       2048
#define AL_OFF      (CCH * STRD * 2)               // 26624 (Ah -> Al offset)
#define OFF_RAW     (OFF_A + 2 * AL_OFF)           // 55296, 10624 fp32 = 42496
#define OFF_BH      (OFF_RAW + GTOT * 4)           // 97792 (256 x 208B)
#define OFF_BL      (OFF_BH + NOUT * STRD * 2)     // 151040
#define SMEM_TOTAL  (OFF_BL + NOUT * STRD * 2)     // 204288 (~199.5 KB)

// W split-bf16 scratch, [0]=hi, [1]=lo, row-major 256 x STRD (pads zeroed)
__device__ __align__(16) __nv_bfloat16 g_B[2][NOUT * STRD];

// ---------------------------------------------------------------------------
__device__ __forceinline__ uint32_t smem_u32(const void* p) {
    uint32_t a;
    asm("{ .reg .u64 t; cvta.to.shared.u64 t, %1; cvt.u32.u64 %0, t; }"
        : "=r"(a) : "l"(p));
    return a;
}

__device__ __forceinline__ void cp16(uint32_t dst, const void* src) {
    asm volatile("cp.async.cg.shared.global [%0], [%1], 16;"
                 :: "r"(dst), "l"(src) : "memory");
}

__device__ __forceinline__ void cp4(uint32_t dst, const void* src) {
    asm volatile("cp.async.ca.shared.global [%0], [%1], 4;"
                 :: "r"(dst), "l"(src) : "memory");
}

__device__ __forceinline__ void ldsm4(uint32_t* r, uint32_t addr) {
    asm volatile("ldmatrix.sync.aligned.m8n8.x4.shared.b16 {%0,%1,%2,%3}, [%4];"
                 : "=r"(r[0]), "=r"(r[1]), "=r"(r[2]), "=r"(r[3]) : "r"(addr));
}

__device__ __forceinline__ void hmma(float* c, const uint32_t* a, const uint32_t* b) {
    asm volatile(
        "mma.sync.aligned.m16n8k16.row.col.f32.bf16.bf16.f32 "
        "{%0,%1,%2,%3}, {%4,%5,%6,%7}, {%8,%9}, {%0,%1,%2,%3};"
        : "+f"(c[0]), "+f"(c[1]), "+f"(c[2]), "+f"(c[3])
        : "r"(a[0]), "r"(a[1]), "r"(a[2]), "r"(a[3]), "r"(b[0]), "r"(b[1]));
}

__device__ __forceinline__ void stcs2(float* p, float x, float y) {
    asm volatile("st.global.cs.v2.f32 [%0], {%1, %2};"
                 :: "l"(p), "f"(x), "f"(y) : "memory");
}

// Per-tap gather metadata for point pn (called with d < 83)
__device__ __forceinline__ void compute_taps(char* smem, int d, int pn,
                                             const float* __restrict__ points,
                                             const float* __restrict__ feat0,
                                             const float* __restrict__ feat1,
                                             const float* __restrict__ feat2) {
    const float* f; int H, Wd, ks, dd;
    if (d < 49)      { f = feat0; H = H0; Wd = W0; ks = 7; dd = d; }
    else if (d < 74) { f = feat1; H = H1; Wd = W1; ks = 5; dd = d - 49; }
    else             { f = feat2; H = H2; Wd = W2; ks = 3; dd = d - 74; }
    int half = ks >> 1;
    int jj = dd / ks - half;
    int kk = dd % ks - half;
    int bi = pn >> 9;
    float px = points[pn * 2 + 0];
    float py = points[pn * 2 + 1];
    float x = fminf(fmaxf(px * (float)(Wd - 1), 0.f), (float)(Wd - 1));
    float y = fminf(fmaxf(py * (float)(H  - 1), 0.f), (float)(H  - 1));
    int ox = (int)floorf(fminf(fmaxf(x + (float)kk, 0.f), (float)(Wd - 1)));
    int oy = (int)floorf(fminf(fmaxf(y + (float)jj, 0.f), (float)(H  - 1)));
    *(int*)(smem + OFF_TAPS + d * 4) = H * Wd;
    *(const float**)(smem + OFF_TAPP + d * 8) =
        f + (size_t)bi * CCH * H * Wd + (oy * Wd + ox);
}

// Issue all gather cp.asyncs for one point into the raw buffer (no waiting).
__device__ __forceinline__ void issue_gather(char* smem, uint32_t raw, int tid) {
    int c = tid / DTOT;
    int d = tid - c * DTOT;
    #pragma unroll 6
    for (int i = 0; i < 42; ++i) {
        int e = tid + 256 * i;
        if (e < GTOT) {
            const float* bp = *(const float* const*)(smem + OFF_TAPP + d * 8);
            int st = *(const int*)(smem + OFF_TAPS + d * 4);
            cp4(raw + e * 4, bp + (size_t)c * st);
        }
        c += 3; d += 7;                 // 256 = 3*83 + 7
        if (d >= DTOT) { d -= DTOT; c += 1; }
    }
}

// Convert raw fp32 gather buffer -> split-bf16 Ah/Al (throughput bound).
__device__ __forceinline__ void convert_raw(char* smem, int tid) {
    const float* raw = (const float*)(smem + OFF_RAW);
    char* ah = smem + OFF_A;
    char* al = smem + OFF_A + AL_OFF;
    int c = tid / DTOT;
    int d = tid - c * DTOT;
    #pragma unroll 6
    for (int i = 0; i < 42; ++i) {
        int e = tid + 256 * i;
        if (e < GTOT) {
            float v = raw[e];
            __nv_bfloat16 hi = __float2bfloat16(v);
            __nv_bfloat16 lo = __float2bfloat16(v - __bfloat162float(hi));
            int sw = c * 208 + d * 2;
            *(__nv_bfloat16*)(ah + sw) = hi;
            *(__nv_bfloat16*)(al + sw) = lo;
        }
        c += 3; d += 7;
        if (d >= DTOT) { d -= DTOT; c += 1; }
    }
}

// ---------------------------------------------------------------------------
// Prologue: W (256x83 fp32) -> g_B hi/lo bf16, row stride STRD, pads zeroed.
__global__ void prep_B_kernel(const float* __restrict__ Wg) {
    int idx = blockIdx.x * 256 + threadIdx.x;
    if (idx >= NOUT * STRD) return;
    int row = idx / STRD;
    int col = idx - row * STRD;
    float v = (col < DTOT) ? Wg[row * DTOT + col] : 0.f;
    __nv_bfloat16 hi = __float2bfloat16(v);
    __nv_bfloat16 lo = __float2bfloat16(v - __bfloat162float(hi));
    g_B[0][idx] = hi;
    g_B[1][idx] = lo;
}

// ---------------------------------------------------------------------------
__global__ void __launch_bounds__(256, 1)
mlfs_kernel(const float* __restrict__ points,
            const float* __restrict__ feat0,
            const float* __restrict__ feat1,
            const float* __restrict__ feat2,
            const float* __restrict__ biasg,
            float* __restrict__ out) {
    extern __shared__ char smem[];
    const uint32_t smem_base = smem_u32(smem);
    const int tid = threadIdx.x;
    const int wid = tid >> 5;
    const int lane = tid & 31;
    const int r = blockIdx.x;

    // ---- setup: B resident copy (async), bias, A-pad zero ----
    {
        const char* src = (const char*)g_B;
        uint32_t dst = smem_base + OFF_BH;
        const int n16 = (2 * NOUT * STRD * 2) / 16;   // 6656
        #pragma unroll 2
        for (int i = tid; i < n16; i += 256)
            cp16(dst + i * 16, src + (size_t)i * 16);
    }
    if (tid < 64)
        ((float4*)(smem + OFF_BIAS))[tid] = ((const float4*)biasg)[tid];

    // zero A pad bytes 160..207 of every row (cols 80..103; convert rewrites
    // 80..82 each point) for Ah and Al: 256 rows
    {
        float4 z = make_float4(0.f, 0.f, 0.f, 0.f);
        int row = tid;                        // 0..255 covers Ah(128)+Al(128)
        char* base = smem + OFF_A + (row >> 7) * AL_OFF + (row & 127) * 208 + 160;
        ((float4*)base)[0] = z; ((float4*)base)[1] = z; ((float4*)base)[2] = z;
    }

    // taps for first point, then issue its gather
    if (tid < DTOT)
        compute_taps(smem, tid, r, points, feat0, feat1, feat2);
    __syncthreads();
    issue_gather(smem, smem_base + OFF_RAW, tid);
    asm volatile("cp.async.commit_group;" ::: "memory");

    // ---- persistent loop ----
    const int wm = wid >> 2;            // 0..1 (M)
    const int wn = wid & 3;             // 0..3 (N within 128-col half)
    const uint32_t lrow = lane & 15;
    const uint32_t kof2 = ((lane >> 4) << 3) * 2;
    const float* bs = (const float*)(smem + OFF_BIAS);

    for (int p = r; p < NPTS_TOTAL; p += NSM) {
        const int pn = p + NSM;
        const bool hasnext = (pn < NPTS_TOTAL);

        asm volatile("cp.async.wait_group 0;" ::: "memory");
        __syncthreads();                 // raw ready; MMA of p-1 done with A

        convert_raw(smem, tid);          // raw -> Ah/Al   (raw now free)
        if (tid < DTOT && hasnext)
            compute_taps(smem, tid, pn, points, feat0, feat1, feat2);
        __syncthreads();                 // A ready; taps ready; raw free

        if (hasnext) {
            issue_gather(smem, smem_base + OFF_RAW, tid);   // fire and forget
            asm volatile("cp.async.commit_group;" ::: "memory");
        }

        // ---- MMA + epilogue on A (overlaps with in-flight cp.asyncs) ----
        float* outp = out + (size_t)p * (CCH * NOUT);
        #pragma unroll
        for (int hh = 0; hh < 2; ++hh) {
            float acc[4][4][4];
            #pragma unroll
            for (int mt = 0; mt < 4; ++mt)
                #pragma unroll
                for (int nt = 0; nt < 4; ++nt)
                    #pragma unroll
                    for (int q = 0; q < 4; ++q) acc[mt][nt][q] = 0.f;

            #pragma unroll
            for (int pass = 0; pass < 3; ++pass) {
                uint32_t aAddr0 = smem_base + OFF_A + ((pass == 2) ? AL_OFF : 0)
                                + (wm * 64 + lrow) * 208 + kof2;
                uint32_t bAddr0 = smem_base + ((pass == 1) ? OFF_BL : OFF_BH)
                                + (hh * 128 + wn * 32 + lrow) * 208 + kof2;
                #pragma unroll
                for (int ks = 0; ks < 6; ++ks) {
                    uint32_t a[4][4], b[4][2], t[4];
                    #pragma unroll
                    for (int mt = 0; mt < 4; ++mt)
                        ldsm4(a[mt], aAddr0 + mt * 16 * 208 + ks * 32);
                    #pragma unroll
                    for (int np = 0; np < 2; ++np) {
                        ldsm4(t, bAddr0 + np * 16 * 208 + ks * 32);
                        b[2 * np + 0][0] = t[0]; b[2 * np + 1][0] = t[1];
                        b[2 * np + 0][1] = t[2]; b[2 * np + 1][1] = t[3];
                    }
                    #pragma unroll
                    for (int mt = 0; mt < 4; ++mt)
                        #pragma unroll
                        for (int nt = 0; nt < 4; ++nt)
                            hmma(acc[mt][nt], a[mt], b[nt]);
                }
            }

            // epilogue for this 128-col half (streaming stores)
            const int r0 = wm * 64 + (lane >> 2);
            const int c0 = wn * 32 + 2 * (lane & 3);
            float2 bv[4];
            #pragma unroll
            for (int nt = 0; nt < 4; ++nt)
                bv[nt] = *(const float2*)(bs + hh * 128 + c0 + nt * 8);
            float* oph = outp + hh * 128;
            #pragma unroll
            for (int mt = 0; mt < 4; ++mt) {
                const int row = r0 + mt * 16;
                #pragma unroll
                for (int nt = 0; nt < 4; ++nt) {
                    const int col = c0 + nt * 8;
                    stcs2(oph + (size_t)row * NOUT + col,
                          acc[mt][nt][0] + bv[nt].x, acc[mt][nt][1] + bv[nt].y);
                    stcs2(oph + (size_t)(row + 8) * NOUT + col,
                          acc[mt][nt][2] + bv[nt].x, acc[mt][nt][3] + bv[nt].y);
                }
            }
        }
    }
}

// ---------------------------------------------------------------------------
extern "C" void kernel_launch(void* const* d_in, const int* in_sizes, int n_in,
                              void* d_out, int out_size) {
    const float* points = (const float*)d_in[0];
    const float* feat0  = (const float*)d_in[1];
    const float* feat1  = (const float*)d_in[2];
    const float* feat2  = (const float*)d_in[3];
    const float* Wg     = (const float*)d_in[4];
    const float* biasg  = (const float*)d_in[5];
    float* out = (float*)d_out;

    prep_B_kernel<<<(NOUT * STRD + 255) / 256, 256>>>(Wg);

    cudaFuncSetAttribute(mlfs_kernel,
                         cudaFuncAttributeMaxDynamicSharedMemorySize, SMEM_TOTAL);
    mlfs_kernel<<<NSM, 256, SMEM_TOTAL>>>(points, feat0, feat1, feat2,
                                          biasg, out);
}

// round 9
// speedup vs baseline: 1.8192x; 1.0926x over previous
#include <cuda_runtime.h>
#include <cuda_bf16.h>
#include <cstdint>

// ---------------------------------------------------------------------------
// MultiLevelFeatureSampler on GB300 (sm_103a via base-target sm_103 SASS)
//
// Per point: D[128x256] = P[128x83] @ W^T (+ bias); P = gather of 83 taps.
// fp32 via split-bf16: D = Ah*Bh + Ah*Bl + Al*Bh, HMMA m16n8k16 fp32 accum.
//
// R9: 512 threads / 16 warps (warp tile 32x32, acc=32 regs, no spill) and a
// MERGED-K mma loop: all three split products share one k-loop and one
// accumulator, so each loaded (ldmatrix) operand feeds 2 HMMAs and the
// per-k-step ldsm count drops 18 -> 12.  Gather of p+1 = fire-and-forget
// cp.async into raw fp32 buffer during MMA of p; output via st.global.cs.
// ---------------------------------------------------------------------------

#define NSM   148
#define NPTS_TOTAL 2048
#define CCH   128
#define DTOT  83
#define GTOT  (CCH * DTOT)     // 10624 gather elements per point
#define STRD  104              // row stride in bf16 (208 B, ldmatrix conflict-free)
#define NOUT  256
#define NTHR  512

#define H0 93
#define W0 305
#define H1 47
#define W1 153
#define H2 24
#define W2 77

// ---- smem layout (bytes) ----
#define OFF_TAPP    0                              // 83 * 8B tap base pointers
#define OFF_TAPS    672                            // 83 * 4B channel strides
#define OFF_BIAS    1008                           // 256 * 4B -> ends 2032
#define OFF_A       2048
#define AL_OFF      (CCH * STRD * 2)               // 26624 (Ah -> Al offset)
#define OFF_RAW     (OFF_A + 2 * AL_OFF)           // 55296, 10624 fp32 = 42496
#define OFF_BH      (OFF_RAW + GTOT * 4)           // 97792 (256 x 208B)
#define OFF_BL      (OFF_BH + NOUT * STRD * 2)     // 151040
#define SMEM_TOTAL  (OFF_BL + NOUT * STRD * 2)     // 204288 (~199.5 KB)

// W split-bf16 scratch, [0]=hi, [1]=lo, row-major 256 x STRD (pads zeroed)
__device__ __align__(16) __nv_bfloat16 g_B[2][NOUT * STRD];

// ---------------------------------------------------------------------------
__device__ __forceinline__ uint32_t smem_u32(const void* p) {
    uint32_t a;
    asm("{ .reg .u64 t; cvta.to.shared.u64 t, %1; cvt.u32.u64 %0, t; }"
        : "=r"(a) : "l"(p));
    return a;
}

__device__ __forceinline__ void cp16(uint32_t dst, const void* src) {
    asm volatile("cp.async.cg.shared.global [%0], [%1], 16;"
                 :: "r"(dst), "l"(src) : "memory");
}

__device__ __forceinline__ void cp4(uint32_t dst, const void* src) {
    asm volatile("cp.async.ca.shared.global [%0], [%1], 4;"
                 :: "r"(dst), "l"(src) : "memory");
}

__device__ __forceinline__ void ldsm4(uint32_t* r, uint32_t addr) {
    asm volatile("ldmatrix.sync.aligned.m8n8.x4.shared.b16 {%0,%1,%2,%3}, [%4];"
                 : "=r"(r[0]), "=r"(r[1]), "=r"(r[2]), "=r"(r[3]) : "r"(addr));
}

__device__ __forceinline__ void hmma(float* c, const uint32_t* a, const uint32_t* b) {
    asm volatile(
        "mma.sync.aligned.m16n8k16.row.col.f32.bf16.bf16.f32 "
        "{%0,%1,%2,%3}, {%4,%5,%6,%7}, {%8,%9}, {%0,%1,%2,%3};"
        : "+f"(c[0]), "+f"(c[1]), "+f"(c[2]), "+f"(c[3])
        : "r"(a[0]), "r"(a[1]), "r"(a[2]), "r"(a[3]), "r"(b[0]), "r"(b[1]));
}

__device__ __forceinline__ void stcs2(float* p, float x, float y) {
    asm volatile("st.global.cs.v2.f32 [%0], {%1, %2};"
                 :: "l"(p), "f"(x), "f"(y) : "memory");
}

// Per-tap gather metadata for point pn (called with d < 83)
__device__ __forceinline__ void compute_taps(char* smem, int d, int pn,
                                             const float* __restrict__ points,
                                             const float* __restrict__ feat0,
                                             const float* __restrict__ feat1,
                                             const float* __restrict__ feat2) {
    const float* f; int H, Wd, ks, dd;
    if (d < 49)      { f = feat0; H = H0; Wd = W0; ks = 7; dd = d; }
    else if (d < 74) { f = feat1; H = H1; Wd = W1; ks = 5; dd = d - 49; }
    else             { f = feat2; H = H2; Wd = W2; ks = 3; dd = d - 74; }
    int half = ks >> 1;
    int jj = dd / ks - half;
    int kk = dd % ks - half;
    int bi = pn >> 9;
    float px = points[pn * 2 + 0];
    float py = points[pn * 2 + 1];
    float x = fminf(fmaxf(px * (float)(Wd - 1), 0.f), (float)(Wd - 1));
    float y = fminf(fmaxf(py * (float)(H  - 1), 0.f), (float)(H  - 1));
    int ox = (int)floorf(fminf(fmaxf(x + (float)kk, 0.f), (float)(Wd - 1)));
    int oy = (int)floorf(fminf(fmaxf(y + (float)jj, 0.f), (float)(H  - 1)));
    *(int*)(smem + OFF_TAPS + d * 4) = H * Wd;
    *(const float**)(smem + OFF_TAPP + d * 8) =
        f + (size_t)bi * CCH * H * Wd + (oy * Wd + ox);
}

// Issue all gather cp.asyncs for one point into the raw buffer (no waiting).
// 512 threads: e = tid + 512*i;  512 = 6*83 + 14.
__device__ __forceinline__ void issue_gather(char* smem, uint32_t raw, int tid) {
    int c = tid / DTOT;
    int d = tid - c * DTOT;
    #pragma unroll 7
    for (int i = 0; i < 21; ++i) {
        int e = tid + NTHR * i;
        if (e < GTOT) {
            const float* bp = *(const float* const*)(smem + OFF_TAPP + d * 8);
            int st = *(const int*)(smem + OFF_TAPS + d * 4);
            cp4(raw + e * 4, bp + (size_t)c * st);
        }
        c += 6; d += 14;
        if (d >= DTOT) { d -= DTOT; c += 1; }
    }
}

// Convert raw fp32 gather buffer -> split-bf16 Ah/Al (throughput bound).
__device__ __forceinline__ void convert_raw(char* smem, int tid) {
    const float* raw = (const float*)(smem + OFF_RAW);
    char* ah = smem + OFF_A;
    char* al = smem + OFF_A + AL_OFF;
    int c = tid / DTOT;
    int d = tid - c * DTOT;
    #pragma unroll 7
    for (int i = 0; i < 21; ++i) {
        int e = tid + NTHR * i;
        if (e < GTOT) {
            float v = raw[e];
            __nv_bfloat16 hi = __float2bfloat16(v);
            __nv_bfloat16 lo = __float2bfloat16(v - __bfloat162float(hi));
            int sw = c * 208 + d * 2;
            *(__nv_bfloat16*)(ah + sw) = hi;
            *(__nv_bfloat16*)(al + sw) = lo;
        }
        c += 6; d += 14;
        if (d >= DTOT) { d -= DTOT; c += 1; }
    }
}

// ---------------------------------------------------------------------------
// Prologue: W (256x83 fp32) -> g_B hi/lo bf16, row stride STRD, pads zeroed.
__global__ void prep_B_kernel(const float* __restrict__ Wg) {
    int idx = blockIdx.x * 256 + threadIdx.x;
    if (idx >= NOUT * STRD) return;
    int row = idx / STRD;
    int col = idx - row * STRD;
    float v = (col < DTOT) ? Wg[row * DTOT + col] : 0.f;
    __nv_bfloat16 hi = __float2bfloat16(v);
    __nv_bfloat16 lo = __float2bfloat16(v - __bfloat162float(hi));
    g_B[0][idx] = hi;
    g_B[1][idx] = lo;
}

// ---------------------------------------------------------------------------
__global__ void __launch_bounds__(NTHR, 1)
mlfs_kernel(const float* __restrict__ points,
            const float* __restrict__ feat0,
            const float* __restrict__ feat1,
            const float* __restrict__ feat2,
            const float* __restrict__ biasg,
            float* __restrict__ out) {
    extern __shared__ char smem[];
    const uint32_t smem_base = smem_u32(smem);
    const int tid = threadIdx.x;
    const int wid = tid >> 5;
    const int lane = tid & 31;
    const int r = blockIdx.x;

    // ---- setup: B resident copy (async), bias, A-pad zero ----
    {
        const char* src = (const char*)g_B;
        uint32_t dst = smem_base + OFF_BH;
        const int n16 = (2 * NOUT * STRD * 2) / 16;   // 6656
        #pragma unroll 2
        for (int i = tid; i < n16; i += NTHR)
            cp16(dst + i * 16, src + (size_t)i * 16);
    }
    if (tid < 64)
        ((float4*)(smem + OFF_BIAS))[tid] = ((const float4*)biasg)[tid];

    // zero A pad bytes 160..207 of every row (cols 80..103; convert rewrites
    // 80..82 each point) for Ah and Al: 256 rows, one per thread tid<256
    if (tid < 256) {
        float4 z = make_float4(0.f, 0.f, 0.f, 0.f);
        int row = tid;
        char* base = smem + OFF_A + (row >> 7) * AL_OFF + (row & 127) * 208 + 160;
        ((float4*)base)[0] = z; ((float4*)base)[1] = z; ((float4*)base)[2] = z;
    }

    // taps for first point, then issue its gather
    if (tid < DTOT)
        compute_taps(smem, tid, r, points, feat0, feat1, feat2);
    __syncthreads();
    issue_gather(smem, smem_base + OFF_RAW, tid);
    asm volatile("cp.async.commit_group;" ::: "memory");

    // ---- persistent loop ----
    const int wm = wid >> 2;            // 0..3 (M, 32-row tiles)
    const int wn = wid & 3;             // 0..3 (N, 32-col tiles within half)
    const uint32_t lrow = lane & 15;
    const uint32_t kof2 = ((lane >> 4) << 3) * 2;
    const float* bs = (const float*)(smem + OFF_BIAS);

    for (int p = r; p < NPTS_TOTAL; p += NSM) {
        const int pn = p + NSM;
        const bool hasnext = (pn < NPTS_TOTAL);

        asm volatile("cp.async.wait_group 0;" ::: "memory");
        __syncthreads();                 // raw ready; MMA of p-1 done with A

        convert_raw(smem, tid);          // raw -> Ah/Al   (raw now free)
        if (tid < DTOT && hasnext)
            compute_taps(smem, tid, pn, points, feat0, feat1, feat2);
        __syncthreads();                 // A ready; taps ready; raw free

        if (hasnext) {
            issue_gather(smem, smem_base + OFF_RAW, tid);   // fire and forget
            asm volatile("cp.async.commit_group;" ::: "memory");
        }

        // ---- merged-K MMA + epilogue (overlaps in-flight cp.asyncs) ----
        float* outp = out + (size_t)p * (CCH * NOUT);
        #pragma unroll
        for (int hh = 0; hh < 2; ++hh) {
            float acc[2][4][4];
            #pragma unroll
            for (int mt = 0; mt < 2; ++mt)
                #pragma unroll
                for (int nt = 0; nt < 4; ++nt)
                    #pragma unroll
                    for (int q = 0; q < 4; ++q) acc[mt][nt][q] = 0.f;

            const uint32_t aAddrH = smem_base + OFF_A
                                  + (wm * 32 + lrow) * 208 + kof2;
            const uint32_t bAddrH = smem_base + OFF_BH
                                  + (hh * 128 + wn * 32 + lrow) * 208 + kof2;
            #pragma unroll
            for (int ks = 0; ks < 6; ++ks) {
                uint32_t ah[2][4], al[2][4], bh[4][2], bl[4][2], t[4];
                #pragma unroll
                for (int mt = 0; mt < 2; ++mt) {
                    ldsm4(ah[mt], aAddrH + mt * 16 * 208 + ks * 32);
                    ldsm4(al[mt], aAddrH + AL_OFF + mt * 16 * 208 + ks * 32);
                }
                #pragma unroll
                for (int np = 0; np < 2; ++np) {
                    ldsm4(t, bAddrH + np * 16 * 208 + ks * 32);
                    bh[2 * np + 0][0] = t[0]; bh[2 * np + 1][0] = t[1];
                    bh[2 * np + 0][1] = t[2]; bh[2 * np + 1][1] = t[3];
                    ldsm4(t, bAddrH + (OFF_BL - OFF_BH) + np * 16 * 208 + ks * 32);
                    bl[2 * np + 0][0] = t[0]; bl[2 * np + 1][0] = t[1];
                    bl[2 * np + 0][1] = t[2]; bl[2 * np + 1][1] = t[3];
                }
                #pragma unroll
                for (int mt = 0; mt < 2; ++mt)
                    #pragma unroll
                    for (int nt = 0; nt < 4; ++nt) {
                        hmma(acc[mt][nt], ah[mt], bh[nt]);
                        hmma(acc[mt][nt], ah[mt], bl[nt]);
                        hmma(acc[mt][nt], al[mt], bh[nt]);
                    }
            }

            // epilogue for this 128-col half (streaming stores)
            const int r0 = wm * 32 + (lane >> 2);
            const int c0 = wn * 32 + 2 * (lane & 3);
            float2 bv[4];
            #pragma unroll
            for (int nt = 0; nt < 4; ++nt)
                bv[nt] = *(const float2*)(bs + hh * 128 + c0 + nt * 8);
            float* oph = outp + hh * 128;
            #pragma unroll
            for (int mt = 0; mt < 2; ++mt) {
                const int row = r0 + mt * 16;
                #pragma unroll
                for (int nt = 0; nt < 4; ++nt) {
                    const int col = c0 + nt * 8;
                    stcs2(oph + (size_t)row * NOUT + col,
                          acc[mt][nt][0] + bv[nt].x, acc[mt][nt][1] + bv[nt].y);
                    stcs2(oph + (size_t)(row + 8) * NOUT + col,
                          acc[mt][nt][2] + bv[nt].x, acc[mt][nt][3] + bv[nt].y);
                }
            }
        }
    }
}

// ---------------------------------------------------------------------------
extern "C" void kernel_launch(void* const* d_in, const int* in_sizes, int n_in,
                              void* d_out, int out_size) {
    const float* points = (const float*)d_in[0];
    const float* feat0  = (const float*)d_in[1];
    const float* feat1  = (const float*)d_in[2];
    const float* feat2  = (const float*)d_in[3];
    const float* Wg     = (const float*)d_in[4];
    const float* biasg  = (const float*)d_in[5];
    float* out = (float*)d_out;

    prep_B_kernel<<<(NOUT * STRD + 255) / 256, 256>>>(Wg);

    cudaFuncSetAttribute(mlfs_kernel,
                         cudaFuncAttributeMaxDynamicSharedMemorySize, SMEM_TOTAL);
    mlfs_kernel<<<NSM, NTHR, SMEM_TOTAL>>>(points, feat0, feat1, feat2,
                                           biasg, out);
}

// round 11
// speedup vs baseline: 2.7021x; 1.4853x over previous
#include <cuda_runtime.h>
#include <cuda_fp16.h>
#include <cstdint>

// ---------------------------------------------------------------------------
// MultiLevelFeatureSampler on GB300 (sm_103a via base-target sm_103 SASS)
//
// Per point: D[128x256] = P[128x83] @ W^T (+ bias); P = gather of 83 taps.
//
// R10: TWO-PRODUCT fp16 scheme.  A (gathered patch) -> single fp16 ah;
// B (static W) -> fp16 split bh + bl with bl = fp16(b - bh).
//   D = ah*bh + ah*bl = ah*(bh+bl) ~= ah*b ;  error = al*b ~ 2^-11 rel
// (predicted rel_err ~2.6e-4, calibrated from R9's measured 4.4e-6 = rho^2).
// -33% HMMA, -25% ldsm, -50% convert STS vs the bf16 3-product kernel.
// Persistent CTAs (grid=148, 512 thr); gather of p+1 = fire-and-forget
// cp.async into raw fp32 smem during MMA of p; resident B; st.global.cs.
// ---------------------------------------------------------------------------

#define NSM   148
#define NPTS_TOTAL 2048
#define CCH   128
#define DTOT  83
#define GTOT  (CCH * DTOT)     // 10624 gather elements per point
#define STRD  104              // row stride in fp16 (208 B, ldmatrix conflict-free)
#define NOUT  256
#define NTHR  512

#define H0 93
#define W0 305
#define H1 47
#define W1 153
#define H2 24
#define W2 77

// ---- smem layout (bytes) ----
#define OFF_TAPP    0                              // 83 * 8B tap base pointers
#define OFF_TAPS    672                            // 83 * 4B channel strides
#define OFF_BIAS    1008                           // 256 * 4B -> ends 2032
#define OFF_A       2048                           // 128 x 208B = 26624 (fp16)
#define OFF_RAW     (OFF_A + CCH * STRD * 2)       // 28672, 10624 fp32 = 42496
#define OFF_BH      (OFF_RAW + GTOT * 4)           // 71168 (256 x 208B fp16)
#define OFF_BL      (OFF_BH + NOUT * STRD * 2)     // 124416
#define SMEM_TOTAL  (OFF_BL + NOUT * STRD * 2)     // 177664 (~173.5 KB)

// W split-fp16 scratch, [0]=hi, [1]=lo, row-major 256 x STRD (pads zeroed)
__device__ __align__(16) __half g_B[2][NOUT * STRD];

// ---------------------------------------------------------------------------
__device__ __forceinline__ uint32_t smem_u32(const void* p) {
    uint32_t a;
    asm("{ .reg .u64 t; cvta.to.shared.u64 t, %1; cvt.u32.u64 %0, t; }"
        : "=r"(a) : "l"(p));
    return a;
}

__device__ __forceinline__ void cp16(uint32_t dst, const void* src) {
    asm volatile("cp.async.cg.shared.global [%0], [%1], 16;"
                 :: "r"(dst), "l"(src) : "memory");
}

__device__ __forceinline__ void cp4(uint32_t dst, const void* src) {
    asm volatile("cp.async.ca.shared.global [%0], [%1], 4;"
                 :: "r"(dst), "l"(src) : "memory");
}

__device__ __forceinline__ void ldsm4(uint32_t* r, uint32_t addr) {
    asm volatile("ldmatrix.sync.aligned.m8n8.x4.shared.b16 {%0,%1,%2,%3}, [%4];"
                 : "=r"(r[0]), "=r"(r[1]), "=r"(r[2]), "=r"(r[3]) : "r"(addr));
}

__device__ __forceinline__ void hmma(float* c, const uint32_t* a, const uint32_t* b) {
    asm volatile(
        "mma.sync.aligned.m16n8k16.row.col.f32.f16.f16.f32 "
        "{%0,%1,%2,%3}, {%4,%5,%6,%7}, {%8,%9}, {%0,%1,%2,%3};"
        : "+f"(c[0]), "+f"(c[1]), "+f"(c[2]), "+f"(c[3])
        : "r"(a[0]), "r"(a[1]), "r"(a[2]), "r"(a[3]), "r"(b[0]), "r"(b[1]));
}

__device__ __forceinline__ void stcs2(float* p, float x, float y) {
    asm volatile("st.global.cs.v2.f32 [%0], {%1, %2};"
                 :: "l"(p), "f"(x), "f"(y) : "memory");
}

// Per-tap gather metadata for point pn (called with d < 83)
__device__ __forceinline__ void compute_taps(char* smem, int d, int pn,
                                             const float* __restrict__ points,
                                             const float* __restrict__ feat0,
                                             const float* __restrict__ feat1,
                                             const float* __restrict__ feat2) {
    const float* f; int H, Wd, ks, dd;
    if (d < 49)      { f = feat0; H = H0; Wd = W0; ks = 7; dd = d; }
    else if (d < 74) { f = feat1; H = H1; Wd = W1; ks = 5; dd = d - 49; }
    else             { f = feat2; H = H2; Wd = W2; ks = 3; dd = d - 74; }
    int half = ks >> 1;
    int jj = dd / ks - half;
    int kk = dd % ks - half;
    int bi = pn >> 9;
    float px = points[pn * 2 + 0];
    float py = points[pn * 2 + 1];
    float x = fminf(fmaxf(px * (float)(Wd - 1), 0.f), (float)(Wd - 1));
    float y = fminf(fmaxf(py * (float)(H  - 1), 0.f), (float)(H  - 1));
    int ox = (int)floorf(fminf(fmaxf(x + (float)kk, 0.f), (float)(Wd - 1)));
    int oy = (int)floorf(fminf(fmaxf(y + (float)jj, 0.f), (float)(H  - 1)));
    *(int*)(smem + OFF_TAPS + d * 4) = H * Wd;
    *(const float**)(smem + OFF_TAPP + d * 8) =
        f + (size_t)bi * CCH * H * Wd + (oy * Wd + ox);
}

// Issue all gather cp.asyncs for one point into the raw buffer (no waiting).
// 512 threads: e = tid + 512*i;  512 = 6*83 + 14.
__device__ __forceinline__ void issue_gather(char* smem, uint32_t raw, int tid) {
    int c = tid / DTOT;
    int d = tid - c * DTOT;
    #pragma unroll 7
    for (int i = 0; i < 21; ++i) {
        int e = tid + NTHR * i;
        if (e < GTOT) {
            const float* bp = *(const float* const*)(smem + OFF_TAPP + d * 8);
            int st = *(const int*)(smem + OFF_TAPS + d * 4);
            cp4(raw + e * 4, bp + (size_t)c * st);
        }
        c += 6; d += 14;
        if (d >= DTOT) { d -= DTOT; c += 1; }
    }
}

// Convert raw fp32 gather buffer -> fp16 A (single product operand).
__device__ __forceinline__ void convert_raw(char* smem, int tid) {
    const float* raw = (const float*)(smem + OFF_RAW);
    char* ah = smem + OFF_A;
    int c = tid / DTOT;
    int d = tid - c * DTOT;
    #pragma unroll 7
    for (int i = 0; i < 21; ++i) {
        int e = tid + NTHR * i;
        if (e < GTOT) {
            *(__half*)(ah + c * 208 + d * 2) = __float2half(raw[e]);
        }
        c += 6; d += 14;
        if (d >= DTOT) { d -= DTOT; c += 1; }
    }
}

// ---------------------------------------------------------------------------
// Prologue: W (256x83 fp32) -> g_B hi/lo fp16, row stride STRD, pads zeroed.
__global__ void prep_B_kernel(const float* __restrict__ Wg) {
    int idx = blockIdx.x * 256 + threadIdx.x;
    if (idx >= NOUT * STRD) return;
    int row = idx / STRD;
    int col = idx - row * STRD;
    float v = (col < DTOT) ? Wg[row * DTOT + col] : 0.f;
    __half hi = __float2half(v);
    __half lo = __float2half(v - __half2float(hi));
    g_B[0][idx] = hi;
    g_B[1][idx] = lo;
}

// ---------------------------------------------------------------------------
__global__ void __launch_bounds__(NTHR, 1)
mlfs_kernel(const float* __restrict__ points,
            const float* __restrict__ feat0,
            const float* __restrict__ feat1,
            const float* __restrict__ feat2,
            const float* __restrict__ biasg,
            float* __restrict__ out) {
    extern __shared__ char smem[];
    const uint32_t smem_base = smem_u32(smem);
    const int tid = threadIdx.x;
    const int wid = tid >> 5;
    const int lane = tid & 31;
    const int r = blockIdx.x;

    // ---- setup: B resident copy (async), bias, A-pad zero ----
    {
        const char* src = (const char*)g_B;
        uint32_t dst = smem_base + OFF_BH;
        const int n16 = (2 * NOUT * STRD * 2) / 16;   // 6656
        #pragma unroll 2
        for (int i = tid; i < n16; i += NTHR)
            cp16(dst + i * 16, src + (size_t)i * 16);
    }
    if (tid < 64)
        ((float4*)(smem + OFF_BIAS))[tid] = ((const float4*)biasg)[tid];

    // zero A pad bytes 160..207 of every row (cols 80..103; convert rewrites
    // 80..82 each point): 128 rows, tid<128
    if (tid < 128) {
        float4 z = make_float4(0.f, 0.f, 0.f, 0.f);
        char* base = smem + OFF_A + tid * 208 + 160;
        ((float4*)base)[0] = z; ((float4*)base)[1] = z; ((float4*)base)[2] = z;
    }

    // taps for first point, then issue its gather
    if (tid < DTOT)
        compute_taps(smem, tid, r, points, feat0, feat1, feat2);
    __syncthreads();
    issue_gather(smem, smem_base + OFF_RAW, tid);
    asm volatile("cp.async.commit_group;" ::: "memory");

    // ---- persistent loop ----
    const int wm = wid >> 2;            // 0..3 (M, 32-row tiles)
    const int wn = wid & 3;             // 0..3 (N, 32-col tiles within half)
    const uint32_t lrow = lane & 15;
    const uint32_t kof2 = ((lane >> 4) << 3) * 2;
    const float* bs = (const float*)(smem + OFF_BIAS);

    for (int p = r; p < NPTS_TOTAL; p += NSM) {
        const int pn = p + NSM;
        const bool hasnext = (pn < NPTS_TOTAL);

        asm volatile("cp.async.wait_group 0;" ::: "memory");
        __syncthreads();                 // raw ready; MMA of p-1 done with A

        convert_raw(smem, tid);          // raw -> fp16 A  (raw now free)
        if (tid < DTOT && hasnext)
            compute_taps(smem, tid, pn, points, feat0, feat1, feat2);
        __syncthreads();                 // A ready; taps ready; raw free

        if (hasnext) {
            issue_gather(smem, smem_base + OFF_RAW, tid);   // fire and forget
            asm volatile("cp.async.commit_group;" ::: "memory");
        }

        // ---- two-product MMA + epilogue (overlaps in-flight cp.asyncs) ----
        float* outp = out + (size_t)p * (CCH * NOUT);
        #pragma unroll
        for (int hh = 0; hh < 2; ++hh) {
            float acc[2][4][4];
            #pragma unroll
            for (int mt = 0; mt < 2; ++mt)
                #pragma unroll
                for (int nt = 0; nt < 4; ++nt)
                    #pragma unroll
                    for (int q = 0; q < 4; ++q) acc[mt][nt][q] = 0.f;

            const uint32_t aAddr0 = smem_base + OFF_A
                                  + (wm * 32 + lrow) * 208 + kof2;
            const uint32_t bAddrH = smem_base + OFF_BH
                                  + (hh * 128 + wn * 32 + lrow) * 208 + kof2;
            #pragma unroll
            for (int ks = 0; ks < 6; ++ks) {
                uint32_t a[2][4], bh[4][2], bl[4][2], t[4];
                #pragma unroll
                for (int mt = 0; mt < 2; ++mt)
                    ldsm4(a[mt], aAddr0 + mt * 16 * 208 + ks * 32);
                #pragma unroll
                for (int np = 0; np < 2; ++np) {
                    ldsm4(t, bAddrH + np * 16 * 208 + ks * 32);
                    bh[2 * np + 0][0] = t[0]; bh[2 * np + 1][0] = t[1];
                    bh[2 * np + 0][1] = t[2]; bh[2 * np + 1][1] = t[3];
                    ldsm4(t, bAddrH + (OFF_BL - OFF_BH) + np * 16 * 208 + ks * 32);
                    bl[2 * np + 0][0] = t[0]; bl[2 * np + 1][0] = t[1];
                    bl[2 * np + 0][1] = t[2]; bl[2 * np + 1][1] = t[3];
                }
                #pragma unroll
                for (int mt = 0; mt < 2; ++mt)
                    #pragma unroll
                    for (int nt = 0; nt < 4; ++nt) {
                        hmma(acc[mt][nt], a[mt], bh[nt]);
                        hmma(acc[mt][nt], a[mt], bl[nt]);
                    }
            }

            // epilogue for this 128-col half (streaming stores)
            const int r0 = wm * 32 + (lane >> 2);
            const int c0 = wn * 32 + 2 * (lane & 3);
            float2 bv[4];
            #pragma unroll
            for (int nt = 0; nt < 4; ++nt)
                bv[nt] = *(const float2*)(bs + hh * 128 + c0 + nt * 8);
            float* oph = outp + hh * 128;
            #pragma unroll
            for (int mt = 0; mt < 2; ++mt) {
                const int row = r0 + mt * 16;
                #pragma unroll
                for (int nt = 0; nt < 4; ++nt) {
                    const int col = c0 + nt * 8;
                    stcs2(oph + (size_t)row * NOUT + col,
                          acc[mt][nt][0] + bv[nt].x, acc[mt][nt][1] + bv[nt].y);
                    stcs2(oph + (size_t)(row + 8) * NOUT + col,
                          acc[mt][nt][2] + bv[nt].x, acc[mt][nt][3] + bv[nt].y);
                }
            }
        }
    }
}

// ---------------------------------------------------------------------------
extern "C" void kernel_launch(void* const* d_in, const int* in_sizes, int n_in,
                              void* d_out, int out_size) {
    const float* points = (const float*)d_in[0];
    const float* feat0  = (const float*)d_in[1];
    const float* feat1  = (const float*)d_in[2];
    const float* feat2  = (const float*)d_in[3];
    const float* Wg     = (const float*)d_in[4];
    const float* biasg  = (const float*)d_in[5];
    float* out = (float*)d_out;

    prep_B_kernel<<<(NOUT * STRD + 255) / 256, 256>>>(Wg);

    cudaFuncSetAttribute(mlfs_kernel,
                         cudaFuncAttributeMaxDynamicSharedMemorySize, SMEM_TOTAL);
    mlfs_kernel<<<NSM, NTHR, SMEM_TOTAL>>>(points, feat0, feat1, feat2,
                                           biasg, out);
}